// round 2
// baseline (speedup 1.0000x reference)
#include <cuda_runtime.h>
#include <cstdio>

#define SEQ      2048
#define BSZ      2
#define DIM      768
#define NH       12
#define HD       64
#define QKV_N    (3*DIM)      // 2304
#define M_ROWS   (BSZ*SEQ)    // 4096

// ---------------- scratch (static device globals; no allocation) ----------------
__device__ float g_qkv[(size_t)M_ROWS * QKV_N];   // [b*s, 2304]  (q|k|v interleaved per row)
__device__ float g_att[(size_t)M_ROWS * DIM];     // [b*s, 768]   merged-head attention output

// ---------------- generic SGEMM with bias: C = A(MxK) * B(KxN) + bias ----------------
// BM=BN=128, BK=16, 256 threads, 8x8 per thread. All dims assumed multiples of tile sizes.
#define BM 128
#define BN 128
#define BK 16

__global__ __launch_bounds__(256)
void sgemm_bias(const float* __restrict__ A, const float* __restrict__ B,
                const float* __restrict__ bias, float* __restrict__ C,
                int M, int N, int K)
{
    __shared__ float As[BK][BM + 4];
    __shared__ float Bs[BK][BN];

    const int tid = threadIdx.x;
    const int bx = blockIdx.x;   // N tiles
    const int by = blockIdx.y;   // M tiles

    const int tx = tid & 15;     // 0..15
    const int ty = tid >> 4;     // 0..15

    float acc[8][8];
    #pragma unroll
    for (int i = 0; i < 8; i++)
        #pragma unroll
        for (int j = 0; j < 8; j++) acc[i][j] = 0.f;

    // A tile loads: 128x16 floats = 512 float4 -> 2 per thread
    const int a_row = tid >> 2;          // 0..63 (and +64)
    const int a_col = (tid & 3) * 4;     // 0,4,8,12
    // B tile loads: 16x128 floats = 512 float4 -> 2 per thread
    const int b_row = tid >> 5;          // 0..7 (and +8)
    const int b_col = (tid & 31) * 4;    // 0..124

    const float* Ab = A + (size_t)(by * BM) * K;
    const float* Bb = B + (size_t)(bx * BN);

    for (int k0 = 0; k0 < K; k0 += BK) {
        #pragma unroll
        for (int i = 0; i < 2; i++) {
            int r = a_row + i * 64;
            float4 v = *(const float4*)(Ab + (size_t)r * K + k0 + a_col);
            As[a_col + 0][r] = v.x;
            As[a_col + 1][r] = v.y;
            As[a_col + 2][r] = v.z;
            As[a_col + 3][r] = v.w;
        }
        #pragma unroll
        for (int i = 0; i < 2; i++) {
            int r = b_row + i * 8;
            float4 v = *(const float4*)(Bb + (size_t)(k0 + r) * N + b_col);
            *(float4*)(&Bs[r][b_col]) = v;
        }
        __syncthreads();

        #pragma unroll
        for (int kk = 0; kk < BK; kk++) {
            float a[8], b[8];
            #pragma unroll
            for (int i = 0; i < 8; i++) a[i] = As[kk][ty * 8 + i];
            #pragma unroll
            for (int j = 0; j < 8; j++) b[j] = Bs[kk][tx * 8 + j];
            #pragma unroll
            for (int i = 0; i < 8; i++)
                #pragma unroll
                for (int j = 0; j < 8; j++)
                    acc[i][j] += a[i] * b[j];
        }
        __syncthreads();
    }

    #pragma unroll
    for (int i = 0; i < 8; i++) {
        const int row = by * BM + ty * 8 + i;
        #pragma unroll
        for (int j = 0; j < 8; j += 4) {
            const int col = bx * BN + tx * 8 + j;
            float4 v;
            v.x = acc[i][j + 0] + bias[col + 0];
            v.y = acc[i][j + 1] + bias[col + 1];
            v.z = acc[i][j + 2] + bias[col + 2];
            v.w = acc[i][j + 3] + bias[col + 3];
            *(float4*)(C + (size_t)row * N + col) = v;
        }
    }
}

// ---------------- flash-style causal attention ----------------
// grid (32 q-tiles, 12 heads, 2 batch), 64 threads; thread t owns query row qt*64+t.
// K/V tiles of 32 rows staged through smem; q, o, scores in registers; online softmax.
#define QT 64
#define KT 32

__global__ __launch_bounds__(64)
void attn_kernel(const float* __restrict__ qkv, float* __restrict__ att)
{
    const int qt = blockIdx.x;
    const int h  = blockIdx.y;
    const int b  = blockIdx.z;
    const int t  = threadIdx.x;
    const int qi = qt * QT + t;                 // global query index within sequence

    __shared__ float sK[KT][HD];
    __shared__ float sV[KT][HD];

    const float scale = 0.125f;                 // 1/sqrt(64)

    const float* qrow = qkv + ((size_t)(b * SEQ + qi)) * QKV_N + h * HD;
    float q[HD];
    #pragma unroll
    for (int d = 0; d < HD; d++) q[d] = qrow[d] * scale;

    float o[HD];
    #pragma unroll
    for (int d = 0; d < HD; d++) o[d] = 0.f;
    float m = -1e30f, l = 0.f;

    const int ntiles = qt * 2 + 2;              // keys [0, (qt+1)*64) in 32-row tiles

    for (int kt = 0; kt < ntiles; kt++) {
        const int s0 = kt * KT;
        const float* kbase = qkv + ((size_t)(b * SEQ + s0)) * QKV_N + DIM + h * HD;
        const float* vbase = kbase + DIM;       // v at +1536 within row

        // cooperative tile load: 512 float4 per matrix, 8 per thread, coalesced
        #pragma unroll
        for (int i = t; i < KT * HD / 4; i += 64) {
            int r = i >> 4;          // / (HD/4)
            int c = (i & 15) * 4;
            *(float4*)(&sK[r][c]) = *(const float4*)(kbase + (size_t)r * QKV_N + c);
            *(float4*)(&sV[r][c]) = *(const float4*)(vbase + (size_t)r * QKV_N + c);
        }
        __syncthreads();

        float sv[KT];
        float smax = -1e30f;
        #pragma unroll
        for (int j = 0; j < KT; j++) {
            float acc = 0.f;
            #pragma unroll
            for (int d = 0; d < HD; d++) acc += q[d] * sK[j][d];
            if (s0 + j > qi) acc = -1e30f;      // causal mask
            sv[j] = acc;
            smax = fmaxf(smax, acc);
        }

        const float mnew = fmaxf(m, smax);
        const float corr = __expf(m - mnew);
        l *= corr;
        #pragma unroll
        for (int d = 0; d < HD; d++) o[d] *= corr;

        #pragma unroll
        for (int j = 0; j < KT; j++) {
            float p = __expf(sv[j] - mnew);
            l += p;
            #pragma unroll
            for (int d = 0; d < HD; d++) o[d] += p * sV[j][d];
        }
        m = mnew;
        __syncthreads();
    }

    const float inv = 1.f / l;
    float* orow = att + ((size_t)(b * SEQ + qi)) * DIM + h * HD;
    #pragma unroll
    for (int d = 0; d < HD; d += 4) {
        float4 v;
        v.x = o[d + 0] * inv;
        v.y = o[d + 1] * inv;
        v.z = o[d + 2] * inv;
        v.w = o[d + 3] * inv;
        *(float4*)(orow + d) = v;
    }
}

// ---------------- launch ----------------
extern "C" void kernel_launch(void* const* d_in, const int* in_sizes, int n_in,
                              void* d_out, int out_size)
{
    const float* x     = (const float*)d_in[0];
    const float* Wqkv  = (const float*)d_in[1];
    const float* bqkv  = (const float*)d_in[2];
    const float* Wproj = (const float*)d_in[3];
    const float* bproj = (const float*)d_in[4];
    float* out = (float*)d_out;

    float* qkv = nullptr;
    float* att = nullptr;
    cudaGetSymbolAddress((void**)&qkv, g_qkv);
    cudaGetSymbolAddress((void**)&att, g_att);

    // 1) QKV projection: [4096,768] @ [768,2304] + b -> g_qkv
    dim3 g1(QKV_N / BN, M_ROWS / BM);
    sgemm_bias<<<g1, 256>>>(x, Wqkv, bqkv, qkv, M_ROWS, QKV_N, DIM);

    // 2) causal flash attention -> g_att  [4096, 768] merged heads
    dim3 g2(SEQ / QT, NH, BSZ);
    attn_kernel<<<g2, 64>>>(qkv, att);

    // 3) output projection: [4096,768] @ [768,768] + b -> out
    dim3 g3(DIM / BN, M_ROWS / BM);
    sgemm_bias<<<g3, 256>>>(att, Wproj, bproj, out, M_ROWS, DIM, DIM);
}